// round 11
// baseline (speedup 1.0000x reference)
#include <cuda_runtime.h>
#include <cstdint>

// Window attention: B_=4096 windows, N=64 tok, C=256, H=8 heads, D=32. fp32 I/O.
//   r0: g_Xr = tf32-round(x)
//   t0: transpose+round w_qkv/w_proj -> g_W*T (tf32)
//   b0: g_BM[h][w] = bias+mask in MMA-fragment order
//   k1: 2-stage cp.async mma.sync tf32 GEMM (float2 frags, KP=40), grid (n,m)
//   k2: mma.sync tf32 attention; no P smem (quad-shfl redistribution); 3 CTAs/SM
//   k3: same GEMM for proj
// (PTX target compute_103: tcgen05 unavailable; legacy mma.sync tf32 path.)

#define NWIN   4096
#define CDIM   256
#define NHEAD  8
#define SCALEF 0.17677669529663687f

__device__ float  g_QKV[(size_t)NWIN * 64 * 768];
__device__ float  g_O  [(size_t)NWIN * 64 * 256];
__device__ float  g_Xr [(size_t)NWIN * 64 * 256];
__device__ float  g_WqkvT [768 * 256];
__device__ float  g_WprojT[256 * 256];
__device__ float4 g_BM[8 * 64 * 1024];      // 8 MB: [h][w][wm][nt][gid][tig]

__device__ __forceinline__ float tf32r(float x) {
    float y; asm("cvt.rna.tf32.f32 %0, %1;" : "=f"(y) : "f"(x)); return y;
}
__device__ __forceinline__ uint32_t smem_u32(const void* p) {
    uint32_t a;
    asm("{ .reg .u64 t; cvta.to.shared.u64 t, %1; cvt.u32.u64 %0, t; }" : "=r"(a) : "l"(p));
    return a;
}
__device__ __forceinline__ void cp_async16(uint32_t dst, const void* src) {
    asm volatile("cp.async.cg.shared.global [%0], [%1], 16;" :: "r"(dst), "l"(src));
}
__device__ __forceinline__ void cp_commit() {
    asm volatile("cp.async.commit_group;" ::: "memory");
}
template<int N> __device__ __forceinline__ void cp_wait() {
    asm volatile("cp.async.wait_group %0;" :: "n"(N) : "memory");
}

// m16n8k8 tf32 mma: D += A(16x8,row) * B(8x8,col).
__device__ __forceinline__ void mma_tf32(float* d, const uint32_t* a, const uint32_t* b) {
    asm volatile(
        "mma.sync.aligned.m16n8k8.row.col.f32.tf32.tf32.f32 "
        "{%0,%1,%2,%3}, {%4,%5,%6,%7}, {%8,%9}, {%0,%1,%2,%3};"
        : "+f"(d[0]), "+f"(d[1]), "+f"(d[2]), "+f"(d[3])
        : "r"(a[0]), "r"(a[1]), "r"(a[2]), "r"(a[3]), "r"(b[0]), "r"(b[1]));
}

// ---------------------------------------------------------------------------
// Kernel r0: elementwise tf32 rounding (float4).
// ---------------------------------------------------------------------------
__global__ void round_tf32(const float4* __restrict__ in, float4* __restrict__ out)
{
    int i = blockIdx.x * blockDim.x + threadIdx.x;
    float4 v = in[i];
    v.x = tf32r(v.x); v.y = tf32r(v.y); v.z = tf32r(v.z); v.w = tf32r(v.w);
    out[i] = v;
}

// ---------------------------------------------------------------------------
// Kernel t0: transpose src[256, ncol] -> dst[ncol, 256], tf32-rounded.
// ---------------------------------------------------------------------------
__global__ void transpose_tf32(const float* __restrict__ src, float* __restrict__ dst, int ncol)
{
    __shared__ float tile[32][33];
    const int bx = blockIdx.x, by = blockIdx.y;
    const int tx = threadIdx.x, ty0 = threadIdx.y;
    #pragma unroll
    for (int j = 0; j < 32; j += 8)
        tile[ty0 + j][tx] = src[(size_t)(by * 32 + ty0 + j) * ncol + bx * 32 + tx];
    __syncthreads();
    #pragma unroll
    for (int j = 0; j < 32; j += 8)
        dst[(size_t)(bx * 32 + ty0 + j) * 256 + by * 32 + tx] = tf32r(tile[tx][ty0 + j]);
}

// ---------------------------------------------------------------------------
// Kernel b0: build bias+mask fragment table (as in R10).
// ---------------------------------------------------------------------------
__global__ void bm_build(const float* __restrict__ mask, const float* __restrict__ bt,
                         float4* __restrict__ out)
{
    const int hw = blockIdx.x;             // 0..511
    const int h = hw >> 6, w = hw & 63;
    const int t = threadIdx.x;             // 256
    const int nt = t >> 5, gid = (t >> 2) & 7, tig = t & 3;
    const float* mrow = mask + (size_t)w * 4096;
    float4* op = out + (size_t)hw * 1024 + nt * 32 + gid * 4 + tig;
    const int c = nt * 8 + tig * 2;
    #pragma unroll
    for (int wm = 0; wm < 4; wm++) {
        const int r0 = wm * 16 + gid, r1 = r0 + 8;
        float4 v;
        v.x = bt[(r0 - c + 63) * 8 + h] + mrow[r0 * 64 + c];
        v.y = bt[(r0 - c + 62) * 8 + h] + mrow[r0 * 64 + c + 1];
        v.z = bt[(r1 - c + 63) * 8 + h] + mrow[r1 * 64 + c];
        v.w = bt[(r1 - c + 62) * 8 + h] + mrow[r1 * 64 + c + 1];
        op[wm * 256] = v;
    }
}

// ---------------------------------------------------------------------------
// Kernel k1/k3: 2-stage cp.async mma.sync tf32 GEMM, float2 fragments.
// Logical-k permutation (slot tig -> k=2*tig, slot tig+4 -> k=2*tig+1) applied
// to BOTH A and B: dot product invariant, fragments become contiguous float2.
// KP=40 (stride==8 mod 32): per-half-warp conflict-free LDS.64.
// ---------------------------------------------------------------------------
#define BM 128
#define BK 32
#define KP 40
#define STG (BM * KP)                       // 5120 floats
#define GEMM_SMEM (2 * 2 * STG * 4)         // 81920 B -> 2 CTAs/SM

__global__ void __launch_bounds__(256, 2) gemm_tf32(
    const float* __restrict__ A, const float* __restrict__ BT,
    const float* __restrict__ bias, float* __restrict__ C, int ncols)
{
    extern __shared__ float sm[];
    float* sA = sm;                         // [2][128][KP]
    float* sB = sm + 2 * STG;               // [2][128][KP]

    const int t = threadIdx.x;
    const int wid = t >> 5, lane = t & 31;
    const int wm = wid & 3, wn = wid >> 2;
    const int gid = lane >> 2, tig = lane & 3;
    const int n0 = blockIdx.x * BM;
    const int m0 = blockIdx.y * BM;
    const uint32_t sAu = smem_u32(sA);
    const uint32_t sBu = smem_u32(sB);

    auto loadAB = [&](int kc, int s) {
        #pragma unroll
        for (int i = 0; i < 4; i++) {
            int f = t + i * 256;
            int r = f >> 3, c4 = f & 7;
            cp_async16(sAu + (uint32_t)(s * STG + r * KP + c4 * 4) * 4,
                       A + (size_t)(m0 + r) * CDIM + kc * BK + c4 * 4);
        }
        #pragma unroll
        for (int i = 0; i < 4; i++) {
            int f = t + i * 256;
            int r = f >> 3, c4 = f & 7;
            cp_async16(sBu + (uint32_t)(s * STG + r * KP + c4 * 4) * 4,
                       BT + (size_t)(n0 + r) * CDIM + kc * BK + c4 * 4);
        }
    };

    float acc[2][8][4];
    #pragma unroll
    for (int mt = 0; mt < 2; mt++)
        #pragma unroll
        for (int nt = 0; nt < 8; nt++)
            #pragma unroll
            for (int e = 0; e < 4; e++) acc[mt][nt][e] = 0.0f;

    loadAB(0, 0); cp_commit();

    #pragma unroll 1
    for (int kc = 0; kc < CDIM / BK; kc++) {
        cp_wait<0>();
        __syncthreads();   // chunk kc visible; all warps done with chunk kc-1
        if (kc + 1 < CDIM / BK) { loadAB(kc + 1, (kc + 1) & 1); cp_commit(); }

        const float* a_s = sA + (kc & 1) * STG;
        const float* b_s = sB + (kc & 1) * STG;
        #pragma unroll
        for (int kk = 0; kk < BK; kk += 8) {
            uint32_t af[2][4], bf[8][2];
            #pragma unroll
            for (int mt = 0; mt < 2; mt++) {
                const float* ap = a_s + (wm * 32 + mt * 16 + gid) * KP + kk + tig * 2;
                float2 a0 = *(const float2*)ap;
                float2 a1 = *(const float2*)(ap + 8 * KP);
                af[mt][0] = __float_as_uint(a0.x);
                af[mt][2] = __float_as_uint(a0.y);
                af[mt][1] = __float_as_uint(a1.x);
                af[mt][3] = __float_as_uint(a1.y);
            }
            #pragma unroll
            for (int nt = 0; nt < 8; nt++) {
                const float* bp = b_s + (wn * 64 + nt * 8 + gid) * KP + kk + tig * 2;
                float2 b0 = *(const float2*)bp;
                bf[nt][0] = __float_as_uint(b0.x);
                bf[nt][1] = __float_as_uint(b0.y);
            }
            #pragma unroll
            for (int mt = 0; mt < 2; mt++)
                #pragma unroll
                for (int nt = 0; nt < 8; nt++)
                    mma_tf32(acc[mt][nt], af[mt], bf[nt]);
        }
    }

    #pragma unroll
    for (int mt = 0; mt < 2; mt++) {
        const int r = m0 + wm * 32 + mt * 16 + gid;
        #pragma unroll
        for (int nt = 0; nt < 8; nt++) {
            const int c = n0 + wn * 64 + nt * 8 + tig * 2;
            float b0 = __ldg(bias + c), b1 = __ldg(bias + c + 1);
            float2 v0 = make_float2(acc[mt][nt][0] + b0, acc[mt][nt][1] + b1);
            float2 v1 = make_float2(acc[mt][nt][2] + b0, acc[mt][nt][3] + b1);
            *(float2*)(C + (size_t)r * ncols + c)       = v0;
            *(float2*)(C + (size_t)(r + 8) * ncols + c) = v1;
        }
    }
}

// ---------------------------------------------------------------------------
// Kernel k2: tensor-core attention, 3 CTAs/SM.
// 2 warp-groups; wg handles head (hp*2+wg), hp=0..3; per-wg named barriers.
// Q/K/V strides 40 (conflict-free float2/scalar frags). NO P smem: softmax
// result redistributed to PV A-fragments via quad shuffles.
// ---------------------------------------------------------------------------
#define WQP 40
#define OFF_Q(wg)  ((wg) * 7680)
#define OFF_K(wg)  ((wg) * 7680 + 2560)
#define OFF_V(wg)  ((wg) * 7680 + 5120)
#define WATTN_SMEM (15360 * 4)              // 61440 B -> 3 CTAs/SM

__global__ void __launch_bounds__(256, 3) wattn(
    const float* __restrict__ qkv, const float4* __restrict__ bmt,
    float* __restrict__ O)
{
    extern __shared__ float sm[];
    const int t = threadIdx.x, wid = t >> 5, lane = t & 31;
    const int wg = wid >> 2, wm = wid & 3;
    const int gid = lane >> 2, tig = lane & 3;
    const int tt = t & 127;
    const int b = blockIdx.x;
    const int barid = 1 + wg;

    float* sQ = sm + OFF_Q(wg);
    float* sK = sm + OFF_K(wg);
    float* sV = sm + OFF_V(wg);

    const float* base = qkv + (size_t)b * (64 * 768);
    float* og = O + (size_t)b * (64 * 256);

    const int r0 = wm * 16 + gid, r1 = r0 + 8;
    const int src0 = (lane & ~3) | (tig >> 1);   // quad lane holding col j=tig
    const int src2 = src0 + 2;                   // quad lane holding col j=tig+4

    for (int hp = 0; hp < 4; hp++) {
        const int h = hp * 2 + wg;
        asm volatile("bar.sync %0, 128;" :: "r"(barid) : "memory");  // prev reads done

        // Stage Q,K,V [64][40] tf32-rounded (float4 LDG + STS).
        #pragma unroll
        for (int i = 0; i < 4; i++) {
            int u = tt + i * 128;
            int n = u >> 3, q = u & 7;
            const float4* rp = (const float4*)(base + n * 768 + h * 32) + q;
            float4 qa = rp[0];
            qa.x = tf32r(qa.x); qa.y = tf32r(qa.y); qa.z = tf32r(qa.z); qa.w = tf32r(qa.w);
            *(float4*)&sQ[n * WQP + q * 4] = qa;
            float4 ka = rp[64];
            ka.x = tf32r(ka.x); ka.y = tf32r(ka.y); ka.z = tf32r(ka.z); ka.w = tf32r(ka.w);
            *(float4*)&sK[n * WQP + q * 4] = ka;
            float4 va = rp[128];
            va.x = tf32r(va.x); va.y = tf32r(va.y); va.z = tf32r(va.z); va.w = tf32r(va.w);
            *(float4*)&sV[n * WQP + q * 4] = va;
        }
        asm volatile("bar.sync %0, 128;" :: "r"(barid) : "memory");  // staging visible

        // Prefetch bias+mask fragments (coalesced LDG.128 from L2).
        float4 bm[8];
        {
            const float4* bmp = bmt + (size_t)((h << 6) | (b & 63)) * 1024
                              + wm * 256 + gid * 4 + tig;
            #pragma unroll
            for (int nt = 0; nt < 8; nt++) bm[nt] = __ldg(bmp + nt * 32);
        }

        // S = Q K^T : float2 fragments (permuted-k; same perm both operands).
        float sacc[8][4];
        #pragma unroll
        for (int nt = 0; nt < 8; nt++)
            #pragma unroll
            for (int e = 0; e < 4; e++) sacc[nt][e] = 0.0f;
        #pragma unroll
        for (int kt = 0; kt < 4; kt++) {
            uint32_t af[4];
            const float* ap = sQ + r0 * WQP + kt * 8 + tig * 2;
            float2 a0 = *(const float2*)ap;
            float2 a1 = *(const float2*)(ap + 8 * WQP);
            af[0] = __float_as_uint(a0.x); af[2] = __float_as_uint(a0.y);
            af[1] = __float_as_uint(a1.x); af[3] = __float_as_uint(a1.y);
            #pragma unroll
            for (int nt = 0; nt < 8; nt++) {
                const float* bp = sK + (nt * 8 + gid) * WQP + kt * 8 + tig * 2;
                float2 b0 = *(const float2*)bp;
                uint32_t bf[2] = { __float_as_uint(b0.x), __float_as_uint(b0.y) };
                mma_tf32(sacc[nt], af, bf);
            }
        }

        // Softmax rows r0,r1; bias+mask from registers.
        float v0[16], v1[16];
        #pragma unroll
        for (int nt = 0; nt < 8; nt++) {
            v0[nt * 2 + 0] = fmaf(sacc[nt][0], SCALEF, bm[nt].x);
            v0[nt * 2 + 1] = fmaf(sacc[nt][1], SCALEF, bm[nt].y);
            v1[nt * 2 + 0] = fmaf(sacc[nt][2], SCALEF, bm[nt].z);
            v1[nt * 2 + 1] = fmaf(sacc[nt][3], SCALEF, bm[nt].w);
        }
        float mx0 = -1e30f, mx1 = -1e30f;
        #pragma unroll
        for (int i = 0; i < 16; i++) { mx0 = fmaxf(mx0, v0[i]); mx1 = fmaxf(mx1, v1[i]); }
        mx0 = fmaxf(mx0, __shfl_xor_sync(0xffffffffu, mx0, 1));
        mx0 = fmaxf(mx0, __shfl_xor_sync(0xffffffffu, mx0, 2));
        mx1 = fmaxf(mx1, __shfl_xor_sync(0xffffffffu, mx1, 1));
        mx1 = fmaxf(mx1, __shfl_xor_sync(0xffffffffu, mx1, 2));
        float s0 = 0.0f, s1 = 0.0f;
        #pragma unroll
        for (int i = 0; i < 16; i++) {
            v0[i] = __expf(v0[i] - mx0); s0 += v0[i];
            v1[i] = __expf(v1[i] - mx1); s1 += v1[i];
        }
        s0 += __shfl_xor_sync(0xffffffffu, s0, 1);
        s0 += __shfl_xor_sync(0xffffffffu, s0, 2);
        s1 += __shfl_xor_sync(0xffffffffu, s1, 1);
        s1 += __shfl_xor_sync(0xffffffffu, s1, 2);
        const float i0 = 1.0f / s0, i1 = 1.0f / s1;
        #pragma unroll
        for (int i = 0; i < 16; i++) {
            v0[i] = tf32r(v0[i] * i0);
            v1[i] = tf32r(v1[i] * i1);
        }

        // O = P @ V : A-fragments via quad shuffles (no smem P).
        // v0[nt*2+e] = P[r0][nt*8+tig*2+e]; need af = P[r][kt*8+tig(+4)].
        float oacc[4][4];
        #pragma unroll
        for (int nt = 0; nt < 4; nt++)
            #pragma unroll
            for (int e = 0; e < 4; e++) oacc[nt][e] = 0.0f;
        const bool odd = (tig & 1);
        #pragma unroll
        for (int kt = 0; kt < 8; kt++) {
            float x0 = __shfl_sync(0xffffffffu, v0[kt * 2 + 0], src0);
            float x1 = __shfl_sync(0xffffffffu, v0[kt * 2 + 1], src0);
            float y0 = __shfl_sync(0xffffffffu, v0[kt * 2 + 0], src2);
            float y1 = __shfl_sync(0xffffffffu, v0[kt * 2 + 1], src2);
            float z0 = __shfl_sync(0xffffffffu, v1[kt * 2 + 0], src0);
            float z1 = __shfl_sync(0xffffffffu, v1[kt * 2 + 1], src0);
            float w0 = __shfl_sync(0xffffffffu, v1[kt * 2 + 0], src2);
            float w1 = __shfl_sync(0xffffffffu, v1[kt * 2 + 1], src2);
            uint32_t af[4];
            af[0] = __float_as_uint(odd ? x1 : x0);   // P[r0][kt*8+tig]
            af[2] = __float_as_uint(odd ? y1 : y0);   // P[r0][kt*8+tig+4]
            af[1] = __float_as_uint(odd ? z1 : z0);   // P[r1][kt*8+tig]
            af[3] = __float_as_uint(odd ? w1 : w0);   // P[r1][kt*8+tig+4]
            #pragma unroll
            for (int nt = 0; nt < 4; nt++) {
                uint32_t bf[2];
                bf[0] = __float_as_uint(sV[(kt * 8 + tig) * WQP + nt * 8 + gid]);
                bf[1] = __float_as_uint(sV[(kt * 8 + tig + 4) * WQP + nt * 8 + gid]);
                mma_tf32(oacc[nt], af, bf);
            }
        }
        #pragma unroll
        for (int nt = 0; nt < 4; nt++) {
            const int c = h * 32 + nt * 8 + tig * 2;
            *(float2*)&og[r0 * 256 + c] =
                make_float2(tf32r(oacc[nt][0]), tf32r(oacc[nt][1]));
            *(float2*)&og[r1 * 256 + c] =
                make_float2(tf32r(oacc[nt][2]), tf32r(oacc[nt][3]));
        }
    }
}

// ---------------------------------------------------------------------------
extern "C" void kernel_launch(void* const* d_in, const int* in_sizes, int n_in,
                              void* d_out, int out_size)
{
    const float* x          = (const float*)d_in[0];
    const float* mask       = (const float*)d_in[1];
    const float* wqkv       = (const float*)d_in[2];
    const float* bqkv       = (const float*)d_in[3];
    const float* wproj      = (const float*)d_in[4];
    const float* bproj      = (const float*)d_in[5];
    const float* bias_table = (const float*)d_in[6];
    (void)in_sizes; (void)n_in; (void)out_size;

    cudaFuncSetAttribute(gemm_tf32, cudaFuncAttributeMaxDynamicSharedMemorySize, GEMM_SMEM);
    cudaFuncSetAttribute(wattn, cudaFuncAttributeMaxDynamicSharedMemorySize, WATTN_SMEM);

    float *qkvT, *projT, *qkvS, *oS, *xr;
    float4* bmT;
    cudaGetSymbolAddress((void**)&qkvT,  g_WqkvT);
    cudaGetSymbolAddress((void**)&projT, g_WprojT);
    cudaGetSymbolAddress((void**)&qkvS,  g_QKV);
    cudaGetSymbolAddress((void**)&oS,    g_O);
    cudaGetSymbolAddress((void**)&xr,    g_Xr);
    cudaGetSymbolAddress((void**)&bmT,   g_BM);

    round_tf32<<<65536, 256>>>((const float4*)x, (float4*)xr);
    transpose_tf32<<<dim3(24, 8), dim3(32, 8)>>>(wqkv,  qkvT, 768);
    transpose_tf32<<<dim3(8, 8),  dim3(32, 8)>>>(wproj, projT, 256);
    bm_build<<<512, 256>>>(mask, bias_table, bmT);
    gemm_tf32<<<dim3(6, 2048), 256, GEMM_SMEM>>>(xr, qkvT, bqkv, qkvS, 768);
    wattn<<<NWIN, 256, WATTN_SMEM>>>(qkvS, bmT, oS);
    gemm_tf32<<<dim3(2, 2048), 256, GEMM_SMEM>>>(oS, projT, bproj, (float*)d_out, 256);
}